// round 5
// baseline (speedup 1.0000x reference)
#include <cuda_runtime.h>
#include <cstdint>

// Problem constants
#define NN     8192
#define HH     1024
#define B0     64
#define FF     2048
#define OO     2048
#define NBLK   6
#define XW     (HH + B0 + FF)   // 3136

// ---------------- scratch buffers (device globals; no allocation) ----------------
__device__ float g_q    [NN * FF];
__device__ float g_sumq [NN * FF];
__device__ float g_resS [NN * FF];
__device__ float g_Aq   [NN * FF];
__device__ float g_sumh [NN * HH];
__device__ float g_resqh[NN * HH];
__device__ float g_Dh   [NN * HH];
__device__ float g_h    [NN * HH];

// ---------------- elementwise: q = pi/4 * d^2, d = x[:, 1088:3136] ----------------
__global__ void square_k(const float* __restrict__ x, float* __restrict__ q) {
    int i = blockIdx.x * blockDim.x + threadIdx.x;   // over NN * FF / 4
    // FF/4 = 512 float4 per row
    int row = i >> 9;
    int col = i & 511;
    const float c = 0.78539816339744830962f; // pi/4
    float4 v = *(const float4*)(x + (size_t)row * XW + (HH + B0) + col * 4);
    float4 o;
    o.x = c * v.x * v.x;
    o.y = c * v.y * v.y;
    o.z = c * v.z * v.z;
    o.w = c * v.w * v.w;
    *(float4*)(q + ((size_t)i << 2)) = o;
}

// ---------------- generic fused GEMM: C = epi( fuseA(A...) @ B^T + bias ) ----------------
// AMODE: 0: a = A0
//        1: a = A0 * A1
//        2: a = A0 * (A1 + A2)
//        3: a = (A0 + A1 + A2) * A3
// EMODE: 0: C = v + bias
//        1: C = relu(v + bias)
//        2: C = C + v + bias                (accumulate)
//        3: z = leaky(v + bias, alpha); C = qin - z
// A0 has row stride lda0; A1..A3 are dense with row stride K.
#define TM 128
#define TN 128
#define TK 16

template<int AMODE, int EMODE>
__global__ __launch_bounds__(256, 2) void gemm_k(
    const float* __restrict__ A0, int lda0,
    const float* __restrict__ A1,
    const float* __restrict__ A2,
    const float* __restrict__ A3,
    const float* __restrict__ B,     // [Nn, K] row-major
    const float* __restrict__ bias,  // [Nn]
    float* __restrict__ C,           // [M, Nn]
    const float* __restrict__ qin,   // EMODE 3
    const float* __restrict__ alpha_ptr, int alpha_idx,
    int M, int Nn, int K)
{
    __shared__ float As[TK][TM];
    __shared__ float Bs[TK][TN];

    const int tid = threadIdx.x;
    const int tx = tid & 15;     // 0..15  (cols)
    const int ty = tid >> 4;     // 0..15  (rows)
    const int bm = blockIdx.y * TM;
    const int bn = blockIdx.x * TN;

    const int arow = tid >> 2;        // 0..63
    const int acol = (tid & 3) * 4;   // 0,4,8,12

    float acc[8][8];
#pragma unroll
    for (int i = 0; i < 8; i++)
#pragma unroll
        for (int j = 0; j < 8; j++) acc[i][j] = 0.f;

    for (int k0 = 0; k0 < K; k0 += TK) {
        // ---- load A tile (with fusion) ----
#pragma unroll
        for (int r = 0; r < 2; r++) {
            int m = arow + r * 64;
            size_t gm = (size_t)(bm + m);
            float4 v = *(const float4*)(A0 + gm * (size_t)lda0 + k0 + acol);
            if (AMODE == 1) {
                float4 w = *(const float4*)(A1 + gm * (size_t)K + k0 + acol);
                v.x *= w.x; v.y *= w.y; v.z *= w.z; v.w *= w.w;
            } else if (AMODE == 2) {
                float4 w1 = *(const float4*)(A1 + gm * (size_t)K + k0 + acol);
                float4 w2 = *(const float4*)(A2 + gm * (size_t)K + k0 + acol);
                v.x *= (w1.x + w2.x); v.y *= (w1.y + w2.y);
                v.z *= (w1.z + w2.z); v.w *= (w1.w + w2.w);
            } else if (AMODE == 3) {
                float4 w1 = *(const float4*)(A1 + gm * (size_t)K + k0 + acol);
                float4 w2 = *(const float4*)(A2 + gm * (size_t)K + k0 + acol);
                float4 w3 = *(const float4*)(A3 + gm * (size_t)K + k0 + acol);
                v.x = (v.x + w1.x + w2.x) * w3.x;
                v.y = (v.y + w1.y + w2.y) * w3.y;
                v.z = (v.z + w1.z + w2.z) * w3.z;
                v.w = (v.w + w1.w + w2.w) * w3.w;
            }
            As[acol + 0][m] = v.x;
            As[acol + 1][m] = v.y;
            As[acol + 2][m] = v.z;
            As[acol + 3][m] = v.w;
        }
        // ---- load B tile ----
#pragma unroll
        for (int r = 0; r < 2; r++) {
            int n = arow + r * 64;
            float4 v = *(const float4*)(B + (size_t)(bn + n) * K + k0 + acol);
            Bs[acol + 0][n] = v.x;
            Bs[acol + 1][n] = v.y;
            Bs[acol + 2][n] = v.z;
            Bs[acol + 3][n] = v.w;
        }
        __syncthreads();

#pragma unroll
        for (int kk = 0; kk < TK; kk++) {
            float af[8], bf[8];
#pragma unroll
            for (int i = 0; i < 8; i++) af[i] = As[kk][ty * 8 + i];
#pragma unroll
            for (int j = 0; j < 8; j++) bf[j] = Bs[kk][tx * 8 + j];
#pragma unroll
            for (int i = 0; i < 8; i++)
#pragma unroll
                for (int j = 0; j < 8; j++) acc[i][j] += af[i] * bf[j];
        }
        __syncthreads();
    }

    float alpha = 0.f;
    if (EMODE == 3) alpha = alpha_ptr[alpha_idx];

#pragma unroll
    for (int i = 0; i < 8; i++) {
        size_t gm = (size_t)(bm + ty * 8 + i);
#pragma unroll
        for (int j = 0; j < 8; j++) {
            int gn = bn + tx * 8 + j;
            float v = acc[i][j] + bias[gn];
            size_t idx = gm * (size_t)Nn + gn;
            if (EMODE == 0) {
                C[idx] = v;
            } else if (EMODE == 1) {
                C[idx] = fmaxf(v, 0.f);
            } else if (EMODE == 2) {
                C[idx] = C[idx] + v;
            } else { // EMODE == 3
                float z = (v >= 0.f) ? v : alpha * v;
                C[idx] = qin[idx] - z;
            }
        }
    }
}

// ---------------- host launch ----------------
static inline dim3 gemm_grid(int M, int Nn) { return dim3(Nn / TN, M / TM); }

extern "C" void kernel_launch(void* const* d_in, const int* in_sizes, int n_in,
                              void* d_out, int out_size)
{
    const float* x      = (const float*)d_in[0];
    const float* W_h0q  = (const float*)d_in[1];
    const float* b_h0q  = (const float*)d_in[2];
    const float* W_sq   = (const float*)d_in[3];
    const float* b_sq   = (const float*)d_in[4];
    const float* W_h0h  = (const float*)d_in[5];
    const float* b_h0h  = (const float*)d_in[6];
    const float* W_S    = (const float*)d_in[7];
    const float* b_S    = (const float*)d_in[8];
    const float* W_q0h  = (const float*)d_in[9];
    const float* b_q0h  = (const float*)d_in[10];
    const float* Wb_Aq  = (const float*)d_in[11];
    const float* bb_Aq  = (const float*)d_in[12];
    const float* Wb_Dh  = (const float*)d_in[13];
    const float* bb_Dh  = (const float*)d_in[14];
    const float* Wb_fh  = (const float*)d_in[15];
    const float* bb_fh  = (const float*)d_in[16];
    const float* Wb_hf  = (const float*)d_in[17];
    const float* bb_hf  = (const float*)d_in[18];
    const float* a_hf   = (const float*)d_in[19];
    const float* Wb_resq= (const float*)d_in[20];
    const float* bb_resq= (const float*)d_in[21];
    const float* W_out  = (const float*)d_in[22];
    const float* b_out  = (const float*)d_in[23];
    float* out = (float*)d_out;

    float *q, *sumq, *sumh, *resS, *resqh, *Aq, *Dh, *h;
    cudaGetSymbolAddress((void**)&q,     g_q);
    cudaGetSymbolAddress((void**)&sumq,  g_sumq);
    cudaGetSymbolAddress((void**)&sumh,  g_sumh);
    cudaGetSymbolAddress((void**)&resS,  g_resS);
    cudaGetSymbolAddress((void**)&resqh, g_resqh);
    cudaGetSymbolAddress((void**)&Aq,    g_Aq);
    cudaGetSymbolAddress((void**)&Dh,    g_Dh);
    cudaGetSymbolAddress((void**)&h,     g_h);

    const int threads = 256;

    // q = pi/4 * d^2
    square_k<<<(NN * FF / 4) / threads, threads>>>(x, q);

    // sum_q_const = s @ W_sq^T + b_sq
    gemm_k<0, 0><<<gemm_grid(NN, FF), threads>>>(
        x, XW, nullptr, nullptr, nullptr, W_sq, b_sq, sumq,
        nullptr, nullptr, 0, NN, FF, HH);

    // sum_q_const += h0 @ W_h0q^T + b_h0q
    gemm_k<0, 2><<<gemm_grid(NN, FF), threads>>>(
        x + HH, XW, nullptr, nullptr, nullptr, W_h0q, b_h0q, sumq,
        nullptr, nullptr, 0, NN, FF, B0);

    // sum_h_const = h0 @ W_h0h^T + b_h0h
    gemm_k<0, 0><<<gemm_grid(NN, HH), threads>>>(
        x + HH, XW, nullptr, nullptr, nullptr, W_h0h, b_h0h, sumh,
        nullptr, nullptr, 0, NN, HH, B0);

    // res_S_q = relu(d @ W_S^T + b_S)
    gemm_k<0, 1><<<gemm_grid(NN, FF), threads>>>(
        x + HH + B0, XW, nullptr, nullptr, nullptr, W_S, b_S, resS,
        nullptr, nullptr, 0, NN, FF, FF);

    // res_q_h = q @ W_q0h^T + b_q0h
    gemm_k<0, 0><<<gemm_grid(NN, HH), threads>>>(
        q, FF, nullptr, nullptr, nullptr, W_q0h, b_q0h, resqh,
        nullptr, nullptr, 0, NN, HH, FF);

    for (int i = 0; i < NBLK; i++) {
        const float* W_Aq_i   = Wb_Aq   + (size_t)i * FF * FF;
        const float* b_Aq_i   = bb_Aq   + (size_t)i * FF;
        const float* W_Dh_i   = Wb_Dh   + (size_t)i * HH * FF;
        const float* b_Dh_i   = bb_Dh   + (size_t)i * HH;
        const float* W_fh_i   = Wb_fh   + (size_t)i * HH * FF;
        const float* b_fh_i   = bb_fh   + (size_t)i * HH;
        const float* W_hf_i   = Wb_hf   + (size_t)i * FF * HH;
        const float* b_hf_i   = bb_hf   + (size_t)i * FF;
        const float* W_resq_i = Wb_resq + (size_t)i * HH * FF;
        const float* b_resq_i = bb_resq + (size_t)i * HH;

        // A_q = (q * res_S_q) @ W_Aq^T + b_Aq
        gemm_k<1, 0><<<gemm_grid(NN, FF), threads>>>(
            q, FF, resS, nullptr, nullptr, W_Aq_i, b_Aq_i, Aq,
            nullptr, nullptr, 0, NN, FF, FF);

        // D_h = relu(A_q @ W_Dh^T + b_Dh)
        gemm_k<0, 1><<<gemm_grid(NN, HH), threads>>>(
            Aq, FF, nullptr, nullptr, nullptr, W_Dh_i, b_Dh_i, Dh,
            nullptr, nullptr, 0, NN, HH, FF);

        // h = relu( (A_q * (q + sum_q_const)) @ W_fh^T + b_fh )
        gemm_k<2, 1><<<gemm_grid(NN, HH), threads>>>(
            Aq, FF, q, sumq, nullptr, W_fh_i, b_fh_i, h,
            nullptr, nullptr, 0, NN, HH, FF);

        // z = ((h + sum_h_const + res_q_h) * D_h) @ W_hf^T + b_hf
        // z = leaky(z, a[i]); q = q - z
        gemm_k<3, 3><<<gemm_grid(NN, FF), threads>>>(
            h, HH, sumh, resqh, Dh, W_hf_i, b_hf_i, q,
            q, a_hf, i, NN, FF, HH);

        // res_q_h = relu(q @ W_resq^T + b_resq)
        gemm_k<0, 1><<<gemm_grid(NN, HH), threads>>>(
            q, FF, nullptr, nullptr, nullptr, W_resq_i, b_resq_i, resqh,
            nullptr, nullptr, 0, NN, HH, FF);
    }

    // out = q @ W_out^T + b_out
    gemm_k<0, 0><<<gemm_grid(NN, OO), threads>>>(
        q, FF, nullptr, nullptr, nullptr, W_out, b_out, out,
        nullptr, nullptr, 0, NN, OO, FF);
}